// round 7
// baseline (speedup 1.0000x reference)
#include <cuda_runtime.h>

#define NB   512
#define NC   16
#define NT   2000
#define NRES 1024
#define NCLS 10
#define NBLK 148
#define ALPHA 0.9f

// Persistent state. Spikes kept in TWO layouts:
//  g_s  [buf][b][j] : classifier reads (identical to round 6)
//  g_sT [buf][j][b] : GEMM A-operand, coalesced LDG per k
__device__ float g_s [2][NB * NRES];
__device__ float g_sT[2][NRES * NB];
__device__ float g_WresT[NRES * NRES];          // Wres^T: [k][j]
__device__ float g_xT[(size_t)NT * NB * NC];    // x^T: [t][b][c]
__device__ unsigned g_bar_count;
__device__ unsigned g_bar_gen;

static __device__ __forceinline__ unsigned ld_acq(const unsigned* p) {
    unsigned v;
    asm volatile("ld.acquire.gpu.global.u32 %0, [%1];" : "=r"(v) : "l"(p) : "memory");
    return v;
}
static __device__ __forceinline__ void st_rel(unsigned* p, unsigned v) {
    asm volatile("st.release.gpu.global.u32 [%0], %1;" :: "l"(p), "r"(v) : "memory");
}

// Grid-wide barrier; all 148 CTAs resident (1 per SM).
static __device__ __forceinline__ void grid_barrier() {
    __syncthreads();
    if (threadIdx.x == 0) {
        unsigned gen = ld_acq(&g_bar_gen);
        __threadfence();
        if (atomicAdd(&g_bar_count, 1u) == NBLK - 1u) {
            g_bar_count = 0u;
            __threadfence();
            st_rel(&g_bar_gen, gen + 1u);
        } else {
            while (ld_acq(&g_bar_gen) == gen) { }
        }
    }
    __syncthreads();
}

__global__ __launch_bounds__(256, 1) void reservoir_persistent(
    const float* __restrict__ x,     // (NB, NC, NT)
    const float* __restrict__ Win,   // (NRES, NC)
    const float* __restrict__ Wres,  // (NRES, NRES)
    const float* __restrict__ Wclf,  // (NCLS, NRES)
    float* __restrict__ out)         // [NB*NCLS | NB*NRES]
{
    const int blk = blockIdx.x;
    const int tid = threadIdx.x;

    __shared__ float sx[64][17];
    __shared__ float sWin[64][17];
    __shared__ float spt[64][68];    // spike tile transpose stage (272B rows, 16B aligned)

    // ---- Phase 0 (all CTAs): one-time transposes ----
    {
        const int g0 = blk * 256 + tid;
        const int gs = NBLK * 256;
        for (int i = g0; i < NRES * NRES; i += gs) {
            int j = i >> 10, k = i & (NRES - 1);
            g_WresT[k * NRES + j] = Wres[i];
        }
        for (size_t i = g0; i < (size_t)NT * NB * NC; i += (size_t)gs) {
            int t = (int)(i >> 13);             // NB*NC = 8192
            int r = (int)(i & 8191);
            int b = r >> 4, c = r & 15;
            g_xT[i] = x[((size_t)(b * NC + c)) * NT + t];
        }
    }

    if (blk < 128) {
        // ---------------- Reservoir path ----------------
        const int b0 = (blk >> 4) * 64;
        const int j0 = (blk & 15) * 64;
        const int ty = tid >> 4;          // row group 0..15
        const int tx = tid & 15;          // col group 0..15

        // Zero step-0 spikes (both layouts), this CTA's tile.
        {
            float4 z = make_float4(0.f, 0.f, 0.f, 0.f);
#pragma unroll
            for (int i = 0; i < 4; i++)
                __stcg((float4*)&g_s[0][(size_t)(b0 + ty * 4 + i) * NRES + j0 + tx * 4], z);
            for (int e = tid; e < 64 * 16; e += 256) {
                int jl = e >> 4, bq = e & 15;
                __stcg((float4*)&g_sT[0][(size_t)(j0 + jl) * NB + b0 + bq * 4], z);
            }
        }
        for (int e = tid; e < 64 * 16; e += 256) {
            int r = e >> 4, c = e & 15;
            sWin[r][c] = Win[(size_t)(j0 + r) * NC + c];
        }

        float v[16], cnt[16];
#pragma unroll
        for (int q = 0; q < 16; q++) { v[q] = 0.f; cnt[q] = 0.f; }

        grid_barrier();

        for (int t = 0; t < NT; ++t) {
            // Stage x_t tile from transposed x (coalesced). Consumed after the
            // post-mainloop __syncthreads.
            {
                const float* xt = &g_xT[(size_t)t * (NB * NC) + (size_t)b0 * NC];
                for (int e = tid; e < 64 * 16; e += 256)
                    sx[e >> 4][e & 15] = xt[e];
            }

            // Mainloop: both operands straight from L2, k strictly DESCENDING.
            // Bit-identical FMA chain to round 6 (same values, same order).
            const float* ap = &g_sT[t & 1][b0 + ty * 4];
            const float* bp = &g_WresT[j0 + tx * 4];

            float acc[4][4];
#pragma unroll
            for (int i = 0; i < 4; i++)
#pragma unroll
                for (int j = 0; j < 4; j++) acc[i][j] = 0.f;

#pragma unroll 8
            for (int k = NRES - 1; k >= 0; --k) {
                float4 a4 = __ldcg((const float4*)(ap + (size_t)k * NB));
                float4 b4 = __ldg ((const float4*)(bp + (size_t)k * NRES));
                float aa[4] = {a4.x, a4.y, a4.z, a4.w};
                float bb[4] = {b4.x, b4.y, b4.z, b4.w};
#pragma unroll
                for (int i = 0; i < 4; i++)
#pragma unroll
                    for (int j = 0; j < 4; j++)
                        acc[i][j] = __fmaf_rn(aa[i], bb[j], acc[i][j]);
            }

            __syncthreads();   // sx staged; spt free from previous step

            // Epilogue (frozen): vn = rn(fma(0.9, v, d_in) + d_rec)
            float* snext = g_s[(t + 1) & 1];
#pragma unroll
            for (int i = 0; i < 4; i++) {
                const int rb = ty * 4 + i;
                float sp[4];
#pragma unroll
                for (int j = 0; j < 4; j++) {
                    const int cj = tx * 4 + j;
                    float d = 0.f;
#pragma unroll
                    for (int c = 0; c < NC; c++)
                        d = __fmaf_rn(sx[rb][c], sWin[cj][c], d);
                    const int q = i * 4 + j;
                    float vn = __fadd_rn(__fmaf_rn(ALPHA, v[q], d), acc[i][j]);
                    float s = (vn >= 1.0f) ? 1.0f : 0.0f;
                    v[q] = (vn >= 1.0f) ? 0.0f : vn;
                    cnt[q] += s;
                    sp[j] = s;
                    spt[cj][rb] = s;
                }
                __stcg((float4*)&snext[(size_t)(b0 + rb) * NRES + j0 + tx * 4],
                       make_float4(sp[0], sp[1], sp[2], sp[3]));
            }
            __syncthreads();
            // Write transposed spikes (coalesced float4 rows).
            {
                float* sTnext = g_sT[(t + 1) & 1];
                for (int e = tid; e < 64 * 16; e += 256) {
                    int jl = e >> 4, bq = e & 15;
                    float4 val = *(const float4*)&spt[jl][bq * 4];
                    __stcg((float4*)&sTnext[(size_t)(j0 + jl) * NB + b0 + bq * 4], val);
                }
            }

            grid_barrier();
        }
        grid_barrier();   // classifier finishes step NT-1

#pragma unroll
        for (int i = 0; i < 4; i++) {
            *(float4*)&out[(size_t)NB * NCLS +
                           (size_t)(b0 + ty * 4 + i) * NRES + j0 + tx * 4] =
                make_float4(cnt[i * 4 + 0], cnt[i * 4 + 1], cnt[i * 4 + 2], cnt[i * 4 + 3]);
        }
    } else {
        // ---------------- Classifier path (numerics unchanged) ----------------
        const int idx = (blk - 128) * 256 + tid;   // 0..5119
        const int b = idx / NCLS;
        const int m = idx % NCLS;
        float vc = 0.f, cc = 0.f;

        grid_barrier();

        for (int t = 0; t <= NT; ++t) {
            if (t >= 1) {
                const float* __restrict__ s_prev = g_s[t & 1];  // spikes of step t-1
                const float* srow = &s_prev[(size_t)b * NRES];
                const float* wrow = &Wclf[(size_t)m * NRES];
                float tot = 0.f;
#pragma unroll
                for (int blkk = 0; blkk < 4; ++blkk) {
                    float a = 0.f;
#pragma unroll 8
                    for (int n = 0; n < 256; n += 4) {
                        int base = blkk * 256 + n;
                        float4 sv = __ldcg((const float4*)(srow + base));
                        float4 wv = *(const float4*)(wrow + base);
                        a = __fmaf_rn(sv.x, wv.x, a);
                        a = __fmaf_rn(sv.y, wv.y, a);
                        a = __fmaf_rn(sv.z, wv.z, a);
                        a = __fmaf_rn(sv.w, wv.w, a);
                    }
                    tot = __fadd_rn(tot, a);
                }
                float vn = __fmaf_rn(ALPHA, vc, tot);
                float s = (vn >= 1.0f) ? 1.0f : 0.0f;
                vc = (vn >= 1.0f) ? 0.0f : vn;
                cc += s;
            }
            grid_barrier();
        }
        out[idx] = cc;
    }
}

extern "C" void kernel_launch(void* const* d_in, const int* in_sizes, int n_in,
                              void* d_out, int out_size) {
    const float* x = 0; const float* Win = 0;
    const float* Wres = 0; const float* Wclf = 0;
    for (int i = 0; i < n_in; ++i) {
        switch (in_sizes[i]) {
            case NB * NC * NT:   x    = (const float*)d_in[i]; break;
            case NRES * NC:      Win  = (const float*)d_in[i]; break;
            case NRES * NRES:    Wres = (const float*)d_in[i]; break;
            case NCLS * NRES:    Wclf = (const float*)d_in[i]; break;
        }
    }
    float* out = (float*)d_out;

    reservoir_persistent<<<NBLK, 256>>>(x, Win, Wres, Wclf, out);
}

// round 8
// speedup vs baseline: 1.4788x; 1.4788x over previous
#include <cuda_runtime.h>

#define NB   512
#define NC   16
#define NT   2000
#define NRES 1024
#define NCLS 10
#define NBLK 148
#define ALPHA 0.9f

// Persistent cross-CTA state: spike double buffer + grid barrier.
__device__ float g_s[2][NB * NRES];
__device__ unsigned g_bar_count;
__device__ unsigned g_bar_gen;

static __device__ __forceinline__ unsigned ld_acq(const unsigned* p) {
    unsigned v;
    asm volatile("ld.acquire.gpu.global.u32 %0, [%1];" : "=r"(v) : "l"(p) : "memory");
    return v;
}
static __device__ __forceinline__ void st_rel(unsigned* p, unsigned v) {
    asm volatile("st.release.gpu.global.u32 [%0], %1;" :: "l"(p), "r"(v) : "memory");
}

// Grid-wide barrier; all 148 CTAs resident (1 per SM).
static __device__ __forceinline__ void grid_barrier() {
    __syncthreads();
    if (threadIdx.x == 0) {
        unsigned gen = ld_acq(&g_bar_gen);
        __threadfence();
        if (atomicAdd(&g_bar_count, 1u) == NBLK - 1u) {
            g_bar_count = 0u;
            __threadfence();
            st_rel(&g_bar_gen, gen + 1u);
        } else {
            while (ld_acq(&g_bar_gen) == gen) { }
        }
    }
    __syncthreads();
}

// Packed helpers. fma.rn.f32x2: two independent fp32 FMAs, each rn —
// per-lane bit-identical to __fmaf_rn. (sm_100+)
static __device__ __forceinline__ unsigned long long pack2(float lo, float hi) {
    unsigned long long r;
    asm("mov.b64 %0, {%1, %2};" : "=l"(r) : "f"(lo), "f"(hi));
    return r;
}
static __device__ __forceinline__ void unpack2(unsigned long long p, float& lo, float& hi) {
    asm("mov.b64 {%0, %1}, %2;" : "=f"(lo), "=f"(hi) : "l"(p));
}
static __device__ __forceinline__ void fma2(unsigned long long& acc,
                                            unsigned long long a,
                                            unsigned long long b) {
    asm("fma.rn.f32x2 %0, %1, %2, %0;" : "+l"(acc) : "l"(a), "l"(b));
}

__global__ __launch_bounds__(256, 1) void reservoir_persistent(
    const float* __restrict__ x,     // (NB, NC, NT)
    const float* __restrict__ Win,   // (NRES, NC)
    const float* __restrict__ Wres,  // (NRES, NRES)
    const float* __restrict__ Wclf,  // (NCLS, NRES)
    float* __restrict__ out)         // [NB*NCLS | NB*NRES]
{
    const int blk = blockIdx.x;
    const int tid = threadIdx.x;

    __shared__ float As[16][68];
    __shared__ float Bs[16][68];
    __shared__ float sx[64][17];
    __shared__ float sWin[64][17];

    if (blk < 128) {
        // ---------------- Reservoir path ----------------
        const int b0 = (blk >> 4) * 64;
        const int j0 = (blk & 15) * 64;

        const int sr = tid >> 2;          // staging row 0..63
        const int sq = tid & 3;           // staging quad
        const int ty = tid >> 4;          // compute row group
        const int tx = tid & 15;          // compute col group

        // Zero this tile of s[0].
        {
            float4 z = make_float4(0.f, 0.f, 0.f, 0.f);
#pragma unroll
            for (int i = 0; i < 4; i++)
                __stcg((float4*)&g_s[0][(size_t)(b0 + ty * 4 + i) * NRES + j0 + tx * 4], z);
        }
        for (int e = tid; e < 64 * 16; e += 256) {
            int r = e >> 4, c = e & 15;
            sWin[r][c] = Win[(size_t)(j0 + r) * NC + c];
        }

        float v[16], cnt[16];
#pragma unroll
        for (int q = 0; q < 16; q++) { v[q] = 0.f; cnt[q] = 0.f; }

        const float* bptr = &Wres[(size_t)(j0 + sr) * NRES + sq * 4];

        grid_barrier();

        for (int t = 0; t < NT; ++t) {
            const float* __restrict__ s_prev = g_s[t & 1];
            float* __restrict__ s_next = g_s[(t + 1) & 1];
            const float* aptr = &s_prev[(size_t)(b0 + sr) * NRES + sq * 4];

            for (int e = tid; e < 64 * 16; e += 256) {
                int r = e >> 4, c = e & 15;
                sx[r][c] = x[((size_t)(b0 + r) * NC + c) * NT + t];
            }

            // Frozen numerics: per output a single accumulator chain over
            // strictly DESCENDING k. Packed f32x2 pairs two j-columns per
            // instruction; each half is an independent rn FMA -> bit-identical.
            unsigned long long acc2[4][2];
#pragma unroll
            for (int i = 0; i < 4; i++) {
                acc2[i][0] = pack2(0.f, 0.f);
                acc2[i][1] = pack2(0.f, 0.f);
            }

            float4 av = __ldcg((const float4*)(aptr + 63 * 16));
            float4 bv = *(const float4*)(bptr + 63 * 16);

            for (int kc = 63; kc >= 0; --kc) {
                __syncthreads();
                As[sq * 4 + 0][sr] = av.x; As[sq * 4 + 1][sr] = av.y;
                As[sq * 4 + 2][sr] = av.z; As[sq * 4 + 3][sr] = av.w;
                Bs[sq * 4 + 0][sr] = bv.x; Bs[sq * 4 + 1][sr] = bv.y;
                Bs[sq * 4 + 2][sr] = bv.z; Bs[sq * 4 + 3][sr] = bv.w;
                __syncthreads();
                if (kc > 0) {
                    av = __ldcg((const float4*)(aptr + (kc - 1) * 16));
                    bv = *(const float4*)(bptr + (kc - 1) * 16);
                }
#pragma unroll
                for (int k = 15; k >= 0; --k) {
                    float4 a4 = *(const float4*)&As[k][ty * 4];
                    float4 b4 = *(const float4*)&Bs[k][tx * 4];
                    unsigned long long b01 = pack2(b4.x, b4.y);
                    unsigned long long b23 = pack2(b4.z, b4.w);
                    float aa[4] = {a4.x, a4.y, a4.z, a4.w};
#pragma unroll
                    for (int i = 0; i < 4; i++) {
                        unsigned long long ai2 = pack2(aa[i], aa[i]);
                        fma2(acc2[i][0], ai2, b01);
                        fma2(acc2[i][1], ai2, b23);
                    }
                }
            }

            float acc[4][4];
#pragma unroll
            for (int i = 0; i < 4; i++) {
                unpack2(acc2[i][0], acc[i][0], acc[i][1]);
                unpack2(acc2[i][1], acc[i][2], acc[i][3]);
            }

            // Epilogue (frozen): vn = rn(fma(0.9, v, d_in) + d_rec)
#pragma unroll
            for (int i = 0; i < 4; i++) {
                const int rb = ty * 4 + i;
                float sp[4];
#pragma unroll
                for (int j = 0; j < 4; j++) {
                    const int cj = tx * 4 + j;
                    float d = 0.f;
#pragma unroll
                    for (int c = 0; c < NC; c++)
                        d = __fmaf_rn(sx[rb][c], sWin[cj][c], d);
                    const int q = i * 4 + j;
                    float vn = __fadd_rn(__fmaf_rn(ALPHA, v[q], d), acc[i][j]);
                    float s = (vn >= 1.0f) ? 1.0f : 0.0f;
                    v[q] = (vn >= 1.0f) ? 0.0f : vn;
                    cnt[q] += s;
                    sp[j] = s;
                }
                __stcg((float4*)&s_next[(size_t)(b0 + rb) * NRES + j0 + tx * 4],
                       make_float4(sp[0], sp[1], sp[2], sp[3]));
            }

            grid_barrier();
        }
        grid_barrier();   // classifier finishes step NT-1

#pragma unroll
        for (int i = 0; i < 4; i++) {
            *(float4*)&out[(size_t)NB * NCLS +
                           (size_t)(b0 + ty * 4 + i) * NRES + j0 + tx * 4] =
                make_float4(cnt[i * 4 + 0], cnt[i * 4 + 1], cnt[i * 4 + 2], cnt[i * 4 + 3]);
        }
    } else {
        // ---------------- Classifier path (numerics unchanged) ----------------
        const int idx = (blk - 128) * 256 + tid;   // 0..5119
        const int b = idx / NCLS;
        const int m = idx % NCLS;
        float vc = 0.f, cc = 0.f;

        grid_barrier();

        for (int t = 0; t <= NT; ++t) {
            if (t >= 1) {
                const float* __restrict__ s_prev = g_s[t & 1];  // spikes of step t-1
                const float* srow = &s_prev[(size_t)b * NRES];
                const float* wrow = &Wclf[(size_t)m * NRES];
                float tot = 0.f;
#pragma unroll
                for (int blkk = 0; blkk < 4; ++blkk) {
                    float a = 0.f;
#pragma unroll 8
                    for (int n = 0; n < 256; n += 4) {
                        int base = blkk * 256 + n;
                        float4 sv = __ldcg((const float4*)(srow + base));
                        float4 wv = *(const float4*)(wrow + base);
                        a = __fmaf_rn(sv.x, wv.x, a);
                        a = __fmaf_rn(sv.y, wv.y, a);
                        a = __fmaf_rn(sv.z, wv.z, a);
                        a = __fmaf_rn(sv.w, wv.w, a);
                    }
                    tot = __fadd_rn(tot, a);
                }
                float vn = __fmaf_rn(ALPHA, vc, tot);
                float s = (vn >= 1.0f) ? 1.0f : 0.0f;
                vc = (vn >= 1.0f) ? 0.0f : vn;
                cc += s;
            }
            grid_barrier();
        }
        out[idx] = cc;
    }
}

extern "C" void kernel_launch(void* const* d_in, const int* in_sizes, int n_in,
                              void* d_out, int out_size) {
    const float* x = 0; const float* Win = 0;
    const float* Wres = 0; const float* Wclf = 0;
    for (int i = 0; i < n_in; ++i) {
        switch (in_sizes[i]) {
            case NB * NC * NT:   x    = (const float*)d_in[i]; break;
            case NRES * NC:      Win  = (const float*)d_in[i]; break;
            case NRES * NRES:    Wres = (const float*)d_in[i]; break;
            case NCLS * NRES:    Wclf = (const float*)d_in[i]; break;
        }
    }
    float* out = (float*)d_out;

    reservoir_persistent<<<NBLK, 256>>>(x, Win, Wres, Wclf, out);
}